// round 1
// baseline (speedup 1.0000x reference)
#include <cuda_runtime.h>
#include <math.h>
#include <stddef.h>

// Problem constants (fixed by reference setup)
#define BB 2
#define SS 2048
#define DD 1024
#define HH 16
#define HD 64
#define NROWS (BB*SS)   // 4096
#define BH (BB*HH)      // 32

// Scratch (static __device__ arrays — allocation-free per harness rules)
__device__ float g_q [(size_t)NROWS*DD];
__device__ float g_k [(size_t)NROWS*DD];
__device__ float g_v [(size_t)NROWS*DD];
__device__ float g_av[(size_t)NROWS*DD];
__device__ float g_scores[(size_t)BH*SS*SS];  // fallback only (attn normally lives in d_out)

// ---------------------------------------------------------------------------
// Projection GEMM: C[M=4096, N=1024] = A[4096,1024] @ W[1024,1024] + bias
// Optional fused relative-position add: rp(s=row%S, j=col) = clip(j-s,-3,3)
// 128x128 block tile, k-step 8, 256 threads, 8x8 per-thread microtile.
// ---------------------------------------------------------------------------
template<bool RELPOS>
__global__ __launch_bounds__(256)
void proj_kernel(const float* __restrict__ A, const float* __restrict__ W,
                 const float* __restrict__ bias, float* __restrict__ C) {
    __shared__ float As[8][128];
    __shared__ float Bs[8][128];
    const int tid  = threadIdx.x;
    const int row0 = blockIdx.y * 128;
    const int col0 = blockIdx.x * 128;
    const int ty = tid >> 4, tx = tid & 15;

    float acc[8][8];
    #pragma unroll
    for (int i = 0; i < 8; i++)
        #pragma unroll
        for (int j = 0; j < 8; j++) acc[i][j] = 0.f;

    const int ar = tid >> 1, ac = (tid & 1) * 4;     // A tile: 128 rows x 8 k
    const int wk = tid >> 5, wn = (tid & 31) * 4;    // W tile: 8 k x 128 n

    for (int k0 = 0; k0 < DD; k0 += 8) {
        float4 av4 = *(const float4*)&A[(size_t)(row0 + ar)*DD + k0 + ac];
        float4 wv4 = *(const float4*)&W[(size_t)(k0 + wk)*DD + col0 + wn];
        __syncthreads();
        As[ac+0][ar] = av4.x; As[ac+1][ar] = av4.y;
        As[ac+2][ar] = av4.z; As[ac+3][ar] = av4.w;
        *(float4*)&Bs[wk][wn] = wv4;
        __syncthreads();
        #pragma unroll
        for (int k = 0; k < 8; k++) {
            float a[8], b[8];
            *(float4*)(a  ) = *(float4*)&As[k][ty*8];
            *(float4*)(a+4) = *(float4*)&As[k][ty*8+4];
            *(float4*)(b  ) = *(float4*)&Bs[k][tx*8];
            *(float4*)(b+4) = *(float4*)&Bs[k][tx*8+4];
            #pragma unroll
            for (int i = 0; i < 8; i++)
                #pragma unroll
                for (int j = 0; j < 8; j++)
                    acc[i][j] = fmaf(a[i], b[j], acc[i][j]);
        }
    }

    #pragma unroll
    for (int i = 0; i < 8; i++) {
        const int grow = row0 + ty*8 + i;
        const int s = grow & (SS - 1);
        #pragma unroll
        for (int j = 0; j < 8; j++) {
            const int col = col0 + tx*8 + j;
            float v = acc[i][j] + bias[col];
            if (RELPOS) {
                int rp = col - s;
                rp = rp < -3 ? -3 : (rp > 3 ? 3 : rp);
                v += (float)rp;
            }
            C[(size_t)grow*DD + col] = v;
        }
    }
}

// ---------------------------------------------------------------------------
// Scores (NT GEMM): per (b,h): S[2048,2048] = Qh[2048,64] @ Kh[2048,64]^T
//   * (1/32) * mask[b,0,qs,ks]  -> raw (pre-softmax) scores into attn buffer
// Head h of q/k is the contiguous block base + b*S*D + h*S*HD, viewed [2048,64].
// ---------------------------------------------------------------------------
__global__ __launch_bounds__(256)
void scores_kernel(const float* __restrict__ mask, float* __restrict__ scores) {
    __shared__ float Qs[32][128];
    __shared__ float Ks[32][128];
    const int tid = threadIdx.x;
    const int bh = blockIdx.z;
    const int b = bh >> 4, h = bh & 15;
    const float* Q = g_q + (size_t)b*SS*DD + (size_t)h*SS*HD;
    const float* K = g_k + (size_t)b*SS*DD + (size_t)h*SS*HD;
    const int qrow0 = blockIdx.y * 128;
    const int krow0 = blockIdx.x * 128;
    const int ty = tid >> 4, tx = tid & 15;

    float acc[8][8];
    #pragma unroll
    for (int i = 0; i < 8; i++)
        #pragma unroll
        for (int j = 0; j < 8; j++) acc[i][j] = 0.f;

    for (int k0 = 0; k0 < HD; k0 += 32) {
        __syncthreads();
        #pragma unroll
        for (int u = 0; u < 4; u++) {
            const int f = tid + u*256;
            const int r = f >> 3, c = (f & 7) * 4;
            float4 qv = *(const float4*)&Q[(size_t)(qrow0 + r)*HD + k0 + c];
            Qs[c+0][r] = qv.x; Qs[c+1][r] = qv.y; Qs[c+2][r] = qv.z; Qs[c+3][r] = qv.w;
            float4 kv = *(const float4*)&K[(size_t)(krow0 + r)*HD + k0 + c];
            Ks[c+0][r] = kv.x; Ks[c+1][r] = kv.y; Ks[c+2][r] = kv.z; Ks[c+3][r] = kv.w;
        }
        __syncthreads();
        #pragma unroll
        for (int k = 0; k < 32; k++) {
            float a[8], bb[8];
            *(float4*)(a  ) = *(float4*)&Qs[k][ty*8];
            *(float4*)(a+4) = *(float4*)&Qs[k][ty*8+4];
            *(float4*)(bb  ) = *(float4*)&Ks[k][tx*8];
            *(float4*)(bb+4) = *(float4*)&Ks[k][tx*8+4];
            #pragma unroll
            for (int i = 0; i < 8; i++)
                #pragma unroll
                for (int j = 0; j < 8; j++)
                    acc[i][j] = fmaf(a[i], bb[j], acc[i][j]);
        }
    }

    const float* mrow = mask + (size_t)b*SS*SS;
    float* srow = scores + (size_t)bh*SS*SS;
    #pragma unroll
    for (int i = 0; i < 8; i++) {
        const int qr = qrow0 + ty*8 + i;
        #pragma unroll
        for (int j = 0; j < 8; j++) {
            const int kc = krow0 + tx*8 + j;
            srow[(size_t)qr*SS + kc] =
                acc[i][j] * 0.03125f * mrow[(size_t)qr*SS + kc];
        }
    }
}

// ---------------------------------------------------------------------------
// Row softmax over S=2048, one warp per row; 64 values/lane held in registers
// so each element is read once and written once (supports in-place).
// ---------------------------------------------------------------------------
__global__ __launch_bounds__(256)
void softmax_kernel(const float* __restrict__ scores, float* __restrict__ attn) {
    const int row  = blockIdx.x * 8 + (threadIdx.x >> 5);
    const int lane = threadIdx.x & 31;
    const float4* src = (const float4*)(scores + (size_t)row * SS);
    float4*       dst = (float4*)(attn + (size_t)row * SS);

    float4 v[16];
    #pragma unroll
    for (int j = 0; j < 16; j++) v[j] = src[lane + 32*j];

    float m = -3.4e38f;
    #pragma unroll
    for (int j = 0; j < 16; j++) {
        m = fmaxf(m, fmaxf(fmaxf(v[j].x, v[j].y), fmaxf(v[j].z, v[j].w)));
    }
    #pragma unroll
    for (int o = 16; o > 0; o >>= 1) m = fmaxf(m, __shfl_xor_sync(0xffffffffu, m, o));

    float sum = 0.f;
    #pragma unroll
    for (int j = 0; j < 16; j++) {
        v[j].x = expf(v[j].x - m); v[j].y = expf(v[j].y - m);
        v[j].z = expf(v[j].z - m); v[j].w = expf(v[j].w - m);
        sum += (v[j].x + v[j].y) + (v[j].z + v[j].w);
    }
    #pragma unroll
    for (int o = 16; o > 0; o >>= 1) sum += __shfl_xor_sync(0xffffffffu, sum, o);

    const float inv = 1.f / sum;
    #pragma unroll
    for (int j = 0; j < 16; j++) {
        v[j].x *= inv; v[j].y *= inv; v[j].z *= inv; v[j].w *= inv;
        dst[lane + 32*j] = v[j];
    }
}

// ---------------------------------------------------------------------------
// AV (NN GEMM): per (b,h): Oh[2048,64] = P[2048,2048] @ Vh[2048,64]
// Written back into contiguous [B,S,D] layout (inverse of the raw reshape).
// 128x64 block tile, k-step 16, 256 threads, 8x4 microtile.
// ---------------------------------------------------------------------------
__global__ __launch_bounds__(256)
void av_kernel(const float* __restrict__ attn) {
    __shared__ float Ps[16][128];
    __shared__ float Vs[16][64];
    const int tid = threadIdx.x;
    const int bh = blockIdx.y;
    const int b = bh >> 4, h = bh & 15;
    const float* P = attn + (size_t)bh*SS*SS;
    const float* V = g_v  + (size_t)b*SS*DD + (size_t)h*SS*HD;
    float*       O = g_av + (size_t)b*SS*DD + (size_t)h*SS*HD;
    const int row0 = blockIdx.x * 128;
    const int ty = tid >> 4, tx = tid & 15;   // rows ty*8.., cols tx*4..

    float acc[8][4];
    #pragma unroll
    for (int i = 0; i < 8; i++)
        #pragma unroll
        for (int j = 0; j < 4; j++) acc[i][j] = 0.f;

    for (int k0 = 0; k0 < SS; k0 += 16) {
        __syncthreads();
        #pragma unroll
        for (int u = 0; u < 2; u++) {
            const int f = tid + u*256;
            const int r = f >> 2, c = (f & 3) * 4;
            float4 pv = *(const float4*)&P[(size_t)(row0 + r)*SS + k0 + c];
            Ps[c+0][r] = pv.x; Ps[c+1][r] = pv.y; Ps[c+2][r] = pv.z; Ps[c+3][r] = pv.w;
        }
        {
            const int k = tid >> 4, n = (tid & 15) * 4;
            *(float4*)&Vs[k][n] = *(const float4*)&V[(size_t)(k0 + k)*HD + n];
        }
        __syncthreads();
        #pragma unroll
        for (int k = 0; k < 16; k++) {
            float a[8], bv[4];
            *(float4*)(a  ) = *(float4*)&Ps[k][ty*8];
            *(float4*)(a+4) = *(float4*)&Ps[k][ty*8+4];
            *(float4*)(bv ) = *(float4*)&Vs[k][tx*4];
            #pragma unroll
            for (int i = 0; i < 8; i++)
                #pragma unroll
                for (int j = 0; j < 4; j++)
                    acc[i][j] = fmaf(a[i], bv[j], acc[i][j]);
        }
    }
    #pragma unroll
    for (int i = 0; i < 8; i++)
        #pragma unroll
        for (int j = 0; j < 4; j++)
            O[(size_t)(row0 + ty*8 + i)*HD + tx*4 + j] = acc[i][j];
}

// ---------------------------------------------------------------------------
extern "C" void kernel_launch(void* const* d_in, const int* in_sizes, int n_in,
                              void* d_out, int out_size) {
    const float* inputs  = (const float*)d_in[0];
    const float* context = (const float*)d_in[1];
    const float* mask    = (const float*)d_in[2];
    const float* Wq = (const float*)d_in[3];
    const float* bq = (const float*)d_in[4];
    const float* Wk = (const float*)d_in[5];
    const float* bk = (const float*)d_in[6];
    const float* Wv = (const float*)d_in[7];
    const float* bv = (const float*)d_in[8];
    const float* Wo = (const float*)d_in[9];
    const float* bo = (const float*)d_in[10];
    // d_in[11] = clip; fixed to 3 by the reference setup (hard-coded to avoid
    // dtype ambiguity of a python scalar input).

    void* p;
    cudaGetSymbolAddress(&p, g_q);      float* qb = (float*)p;
    cudaGetSymbolAddress(&p, g_k);      float* kb = (float*)p;
    cudaGetSymbolAddress(&p, g_v);      float* vb = (float*)p;
    cudaGetSymbolAddress(&p, g_av);     float* avb = (float*)p;
    cudaGetSymbolAddress(&p, g_scores); float* scratch = (float*)p;

    const size_t OUTN = (size_t)NROWS * DD;        // 4,194,304
    const size_t ATTN = (size_t)BH * SS * SS;      // 134,217,728
    const size_t osz = (size_t)out_size;

    float* out_ptr = nullptr;
    float* attn_ptr = nullptr;
    if (osz == OUTN + ATTN)      { out_ptr = (float*)d_out; attn_ptr = (float*)d_out + OUTN; }
    else if (osz == ATTN)        { attn_ptr = (float*)d_out; }
    else                         { out_ptr = (float*)d_out; }

    // Raw scores + normalized attn share one buffer (softmax is in-place).
    float* sbuf = attn_ptr ? attn_ptr : scratch;

    dim3 pgrid(DD/128, NROWS/128);
    proj_kernel<true ><<<pgrid, 256>>>(inputs,  Wq, bq, qb);   // q (+relpos)
    proj_kernel<false><<<pgrid, 256>>>(context, Wk, bk, kb);   // k
    proj_kernel<true ><<<pgrid, 256>>>(context, Wv, bv, vb);   // v (+relpos)

    scores_kernel<<<dim3(SS/128, SS/128, BH), 256>>>(mask, sbuf);
    softmax_kernel<<<(BH*SS)/8, 256>>>(sbuf, sbuf);
    av_kernel<<<dim3(SS/128, BH), 256>>>(sbuf);

    if (out_ptr)
        proj_kernel<false><<<pgrid, 256>>>(avb, Wo, bo, out_ptr);
}

// round 5
// speedup vs baseline: 1.6972x; 1.6972x over previous
#include <cuda_runtime.h>
#include <math.h>
#include <stddef.h>
#include <stdint.h>

// Problem constants (fixed by reference setup)
#define BB 2
#define SS 2048
#define DD 1024
#define HH 16
#define HD 64
#define NROWS (BB*SS)   // 4096
#define BH (BB*HH)      // 32

// Scratch (static __device__ arrays — allocation-free per harness rules)
__device__ float g_q [(size_t)NROWS*DD];
__device__ float g_k [(size_t)NROWS*DD];
__device__ float g_v [(size_t)NROWS*DD];
__device__ float g_av[(size_t)NROWS*DD];
__device__ float g_scores[(size_t)BH*SS*SS];  // fallback only (attn normally lives in d_out)

// ===========================================================================
// tf32 mma.sync helpers (plain sm_103-compatible PTX; no tcgen05 — the
// harness compiles at virtual target compute_103 which rejects sm_103a-only
// instructions)
// ===========================================================================
__device__ __forceinline__ uint32_t f2tf(float f) {
    uint32_t u; asm("cvt.rna.tf32.f32 %0, %1;" : "=r"(u) : "f"(f)); return u;
}
__device__ __forceinline__ void mma8(float* c, const uint32_t* a, const uint32_t* b) {
    asm volatile(
        "mma.sync.aligned.m16n8k8.row.col.f32.tf32.tf32.f32 "
        "{%0,%1,%2,%3}, {%4,%5,%6,%7}, {%8,%9}, {%0,%1,%2,%3};"
        : "+f"(c[0]), "+f"(c[1]), "+f"(c[2]), "+f"(c[3])
        : "r"(a[0]), "r"(a[1]), "r"(a[2]), "r"(a[3]), "r"(b[0]), "r"(b[1]));
}

// SMEM layout note: within each k8 block of 8 slots, slot 2j holds k-col j and
// slot 2j+1 holds k-col j+4, so one LDS.64 at slot 2*(lane&3) yields the
// (k, k+4) register pair every tf32 fragment wants. Row stride 40 words
// (= 8 banks mod 32) makes the 8-row x 4-slot quad access pattern
// conflict-free for both A and B fragment loads.

// ===========================================================================
// tf32 projection: C[4096,1024] = A[4096,1024] @ W[1024,1024] + bias (+relpos)
// CTA tile 128x128, 8 warps (4x2), warp tile 32x64 (2 m-atoms x 8 n-atoms).
// ===========================================================================
template<bool RELPOS>
__global__ __launch_bounds__(256)
void proj_mma(const float* __restrict__ A, const float* __restrict__ W,
              const float* __restrict__ bias, float* __restrict__ C) {
    __shared__ __align__(16) uint32_t As[128][40];
    __shared__ __align__(16) uint32_t Bs[128][40];
    const int tid = threadIdx.x, wid = tid >> 5, lane = tid & 31;
    const int wr = wid >> 1, wc = wid & 1;
    const int qr = lane >> 2, qs = lane & 3;
    const int row0 = blockIdx.y * 128, col0 = blockIdx.x * 128;

    float c[2][8][4];
    #pragma unroll
    for (int i = 0; i < 2; i++)
        #pragma unroll
        for (int j = 0; j < 8; j++)
            #pragma unroll
            for (int t = 0; t < 4; t++) c[i][j][t] = 0.f;

    for (int k0 = 0; k0 < DD; k0 += 32) {
        __syncthreads();
        #pragma unroll
        for (int u = 0; u < 4; u++) {
            const int f = tid + u * 256;
            // A tile [128 rows x 32 k], permuted scatter
            const int r = f >> 3, j = f & 7;
            float4 v = *(const float4*)&A[(size_t)(row0 + r) * DD + k0 + 4 * j];
            uint32_t* d = &As[r][(j >> 1) * 8 + (j & 1)];
            d[0] = f2tf(v.x); d[2] = f2tf(v.y); d[4] = f2tf(v.z); d[6] = f2tf(v.w);
            // B tile: Bs[n][k] = W[k0+k][col0+n]
            const int n = f & 127, kk4 = f >> 7;      // kk4 in 0..7 -> k = 4*kk4..4*kk4+3
            const float* wp = &W[(size_t)(k0 + kk4 * 4) * DD + col0 + n];
            uint32_t* e = &Bs[n][(kk4 >> 1) * 8 + (kk4 & 1)];
            e[0] = f2tf(wp[0]); e[2] = f2tf(wp[DD]);
            e[4] = f2tf(wp[2 * DD]); e[6] = f2tf(wp[3 * DD]);
        }
        __syncthreads();
        #pragma unroll
        for (int k8 = 0; k8 < 4; k8++) {
            uint32_t a[2][4];
            #pragma unroll
            for (int i = 0; i < 2; i++) {
                const int row = wr * 32 + i * 16 + qr;
                uint2 p0 = *(const uint2*)&As[row    ][k8 * 8 + 2 * qs];
                uint2 p1 = *(const uint2*)&As[row + 8][k8 * 8 + 2 * qs];
                a[i][0] = p0.x; a[i][2] = p0.y; a[i][1] = p1.x; a[i][3] = p1.y;
            }
            #pragma unroll
            for (int j = 0; j < 8; j++) {
                uint2 pb = *(const uint2*)&Bs[wc * 64 + j * 8 + qr][k8 * 8 + 2 * qs];
                uint32_t b[2] = { pb.x, pb.y };
                mma8(c[0][j], a[0], b);
                mma8(c[1][j], a[1], b);
            }
        }
    }

    #pragma unroll
    for (int i = 0; i < 2; i++) {
        const int rowA = row0 + wr * 32 + i * 16 + qr;
        const int sA_ = rowA & (SS - 1);
        const int rowB = rowA + 8;
        const int sB_ = rowB & (SS - 1);
        #pragma unroll
        for (int j = 0; j < 8; j++) {
            const int col = col0 + wc * 64 + j * 8 + 2 * qs;
            float2 bb = *(const float2*)&bias[col];
            float o0 = c[i][j][0] + bb.x, o1 = c[i][j][1] + bb.y;
            float o2 = c[i][j][2] + bb.x, o3 = c[i][j][3] + bb.y;
            if (RELPOS) {
                int eA0 = min(max(col     - sA_, -3), 3);
                int eA1 = min(max(col + 1 - sA_, -3), 3);
                int eB0 = min(max(col     - sB_, -3), 3);
                int eB1 = min(max(col + 1 - sB_, -3), 3);
                o0 += (float)eA0; o1 += (float)eA1;
                o2 += (float)eB0; o3 += (float)eB1;
            }
            *(float2*)&C[(size_t)rowA * DD + col] = make_float2(o0, o1);
            *(float2*)&C[(size_t)rowB * DD + col] = make_float2(o2, o3);
        }
    }
}

// ===========================================================================
// tf32 scores: per (b,h): S[2048,2048] = (Qh @ Kh^T) * (1/32) * mask
// CTA tile 128x128, K=64 in 2 chunks of 32.
// ===========================================================================
__global__ __launch_bounds__(256)
void scores_mma(const float* __restrict__ mask, float* __restrict__ scores) {
    __shared__ __align__(16) uint32_t As[128][40];
    __shared__ __align__(16) uint32_t Bs[128][40];
    const int tid = threadIdx.x, wid = tid >> 5, lane = tid & 31;
    const int wr = wid >> 1, wc = wid & 1;
    const int qr = lane >> 2, qs = lane & 3;
    const int bh = blockIdx.z;
    const int b = bh >> 4, h = bh & 15;
    const float* Q = g_q + (size_t)b * SS * DD + (size_t)h * SS * HD;
    const float* K = g_k + (size_t)b * SS * DD + (size_t)h * SS * HD;
    const int qrow0 = blockIdx.y * 128, krow0 = blockIdx.x * 128;

    float c[2][8][4];
    #pragma unroll
    for (int i = 0; i < 2; i++)
        #pragma unroll
        for (int j = 0; j < 8; j++)
            #pragma unroll
            for (int t = 0; t < 4; t++) c[i][j][t] = 0.f;

    #pragma unroll
    for (int cc = 0; cc < 2; cc++) {
        const int k0 = cc * 32;
        __syncthreads();
        #pragma unroll
        for (int u = 0; u < 4; u++) {
            const int f = tid + u * 256;
            const int r = f >> 3, j = f & 7;
            float4 qv = *(const float4*)&Q[(size_t)(qrow0 + r) * HD + k0 + 4 * j];
            uint32_t* d = &As[r][(j >> 1) * 8 + (j & 1)];
            d[0] = f2tf(qv.x); d[2] = f2tf(qv.y); d[4] = f2tf(qv.z); d[6] = f2tf(qv.w);
            float4 kv = *(const float4*)&K[(size_t)(krow0 + r) * HD + k0 + 4 * j];
            uint32_t* e = &Bs[r][(j >> 1) * 8 + (j & 1)];
            e[0] = f2tf(kv.x); e[2] = f2tf(kv.y); e[4] = f2tf(kv.z); e[6] = f2tf(kv.w);
        }
        __syncthreads();
        #pragma unroll
        for (int k8 = 0; k8 < 4; k8++) {
            uint32_t a[2][4];
            #pragma unroll
            for (int i = 0; i < 2; i++) {
                const int row = wr * 32 + i * 16 + qr;
                uint2 p0 = *(const uint2*)&As[row    ][k8 * 8 + 2 * qs];
                uint2 p1 = *(const uint2*)&As[row + 8][k8 * 8 + 2 * qs];
                a[i][0] = p0.x; a[i][2] = p0.y; a[i][1] = p1.x; a[i][3] = p1.y;
            }
            #pragma unroll
            for (int j = 0; j < 8; j++) {
                uint2 pb = *(const uint2*)&Bs[wc * 64 + j * 8 + qr][k8 * 8 + 2 * qs];
                uint32_t b2[2] = { pb.x, pb.y };
                mma8(c[0][j], a[0], b2);
                mma8(c[1][j], a[1], b2);
            }
        }
    }

    const float* mrow = mask + (size_t)b * SS * SS;
    float* srow = scores + (size_t)bh * SS * SS;
    #pragma unroll
    for (int i = 0; i < 2; i++) {
        const int rowA = qrow0 + wr * 32 + i * 16 + qr;
        const int rowB = rowA + 8;
        #pragma unroll
        for (int j = 0; j < 8; j++) {
            const int col = krow0 + wc * 64 + j * 8 + 2 * qs;
            float2 mA = *(const float2*)&mrow[(size_t)rowA * SS + col];
            float2 mB = *(const float2*)&mrow[(size_t)rowB * SS + col];
            *(float2*)&srow[(size_t)rowA * SS + col] =
                make_float2(c[i][j][0] * 0.03125f * mA.x, c[i][j][1] * 0.03125f * mA.y);
            *(float2*)&srow[(size_t)rowB * SS + col] =
                make_float2(c[i][j][2] * 0.03125f * mB.x, c[i][j][3] * 0.03125f * mB.y);
        }
    }
}

// ===========================================================================
// tf32 AV: per (b,h): Oh[2048,64] = P[2048,2048] @ Vh[2048,64]
// CTA tile 128x64, 8 warps (4x2), warp tile 32x32 (2 m-atoms x 4 n-atoms).
// ===========================================================================
__global__ __launch_bounds__(256)
void av_mma(const float* __restrict__ attn) {
    __shared__ __align__(16) uint32_t As[128][40];
    __shared__ __align__(16) uint32_t Bs[64][40];
    const int tid = threadIdx.x, wid = tid >> 5, lane = tid & 31;
    const int wr = wid >> 1, wc = wid & 1;
    const int qr = lane >> 2, qs = lane & 3;
    const int bh = blockIdx.y;
    const int b = bh >> 4, h = bh & 15;
    const float* P = attn + (size_t)bh * SS * SS;
    const float* V = g_v  + (size_t)b * SS * DD + (size_t)h * SS * HD;
    float*       O = g_av + (size_t)b * SS * DD + (size_t)h * SS * HD;
    const int row0 = blockIdx.x * 128;

    float c[2][4][4];
    #pragma unroll
    for (int i = 0; i < 2; i++)
        #pragma unroll
        for (int j = 0; j < 4; j++)
            #pragma unroll
            for (int t = 0; t < 4; t++) c[i][j][t] = 0.f;

    for (int k0 = 0; k0 < SS; k0 += 32) {
        __syncthreads();
        #pragma unroll
        for (int u = 0; u < 4; u++) {
            const int f = tid + u * 256;
            const int r = f >> 3, j = f & 7;
            float4 pv = *(const float4*)&P[(size_t)(row0 + r) * SS + k0 + 4 * j];
            uint32_t* d = &As[r][(j >> 1) * 8 + (j & 1)];
            d[0] = f2tf(pv.x); d[2] = f2tf(pv.y); d[4] = f2tf(pv.z); d[6] = f2tf(pv.w);
        }
        #pragma unroll
        for (int u = 0; u < 2; u++) {
            const int f = tid + u * 256;          // 512 float4 slots: 16 per k-row
            const int n4 = f & 15, k = f >> 4;    // k in 0..31
            float4 vv = *(const float4*)&V[(size_t)(k0 + k) * HD + n4 * 4];
            const int slot = (k >> 3) * 8 + (k & 3) * 2 + (((k & 7) >= 4) ? 1 : 0);
            Bs[n4 * 4 + 0][slot] = f2tf(vv.x);
            Bs[n4 * 4 + 1][slot] = f2tf(vv.y);
            Bs[n4 * 4 + 2][slot] = f2tf(vv.z);
            Bs[n4 * 4 + 3][slot] = f2tf(vv.w);
        }
        __syncthreads();
        #pragma unroll
        for (int k8 = 0; k8 < 4; k8++) {
            uint32_t a[2][4];
            #pragma unroll
            for (int i = 0; i < 2; i++) {
                const int row = wr * 32 + i * 16 + qr;
                uint2 p0 = *(const uint2*)&As[row    ][k8 * 8 + 2 * qs];
                uint2 p1 = *(const uint2*)&As[row + 8][k8 * 8 + 2 * qs];
                a[i][0] = p0.x; a[i][2] = p0.y; a[i][1] = p1.x; a[i][3] = p1.y;
            }
            #pragma unroll
            for (int j = 0; j < 4; j++) {
                uint2 pb = *(const uint2*)&Bs[wc * 32 + j * 8 + qr][k8 * 8 + 2 * qs];
                uint32_t b2[2] = { pb.x, pb.y };
                mma8(c[0][j], a[0], b2);
                mma8(c[1][j], a[1], b2);
            }
        }
    }

    #pragma unroll
    for (int i = 0; i < 2; i++) {
        const int rowA = row0 + wr * 32 + i * 16 + qr;
        const int rowB = rowA + 8;
        #pragma unroll
        for (int j = 0; j < 4; j++) {
            const int col = wc * 32 + j * 8 + 2 * qs;
            *(float2*)&O[(size_t)rowA * HD + col] = make_float2(c[i][j][0], c[i][j][1]);
            *(float2*)&O[(size_t)rowB * HD + col] = make_float2(c[i][j][2], c[i][j][3]);
        }
    }
}

// ---------------------------------------------------------------------------
// FFMA projection GEMM (fp32 output projection — protects the error budget)
// ---------------------------------------------------------------------------
template<bool RELPOS>
__global__ __launch_bounds__(256)
void proj_kernel(const float* __restrict__ A, const float* __restrict__ W,
                 const float* __restrict__ bias, float* __restrict__ C) {
    __shared__ float As[8][128];
    __shared__ float Bs[8][128];
    const int tid  = threadIdx.x;
    const int row0 = blockIdx.y * 128;
    const int col0 = blockIdx.x * 128;
    const int ty = tid >> 4, tx = tid & 15;

    float acc[8][8];
    #pragma unroll
    for (int i = 0; i < 8; i++)
        #pragma unroll
        for (int j = 0; j < 8; j++) acc[i][j] = 0.f;

    const int ar = tid >> 1, ac = (tid & 1) * 4;
    const int wk = tid >> 5, wn = (tid & 31) * 4;

    for (int k0 = 0; k0 < DD; k0 += 8) {
        float4 av4 = *(const float4*)&A[(size_t)(row0 + ar)*DD + k0 + ac];
        float4 wv4 = *(const float4*)&W[(size_t)(k0 + wk)*DD + col0 + wn];
        __syncthreads();
        As[ac+0][ar] = av4.x; As[ac+1][ar] = av4.y;
        As[ac+2][ar] = av4.z; As[ac+3][ar] = av4.w;
        *(float4*)&Bs[wk][wn] = wv4;
        __syncthreads();
        #pragma unroll
        for (int k = 0; k < 8; k++) {
            float a[8], b[8];
            *(float4*)(a  ) = *(float4*)&As[k][ty*8];
            *(float4*)(a+4) = *(float4*)&As[k][ty*8+4];
            *(float4*)(b  ) = *(float4*)&Bs[k][tx*8];
            *(float4*)(b+4) = *(float4*)&Bs[k][tx*8+4];
            #pragma unroll
            for (int i = 0; i < 8; i++)
                #pragma unroll
                for (int j = 0; j < 8; j++)
                    acc[i][j] = fmaf(a[i], b[j], acc[i][j]);
        }
    }

    #pragma unroll
    for (int i = 0; i < 8; i++) {
        const int grow = row0 + ty*8 + i;
        const int s = grow & (SS - 1);
        #pragma unroll
        for (int j = 0; j < 8; j++) {
            const int col = col0 + tx*8 + j;
            float v = acc[i][j] + bias[col];
            if (RELPOS) {
                int rp = col - s;
                rp = rp < -3 ? -3 : (rp > 3 ? 3 : rp);
                v += (float)rp;
            }
            C[(size_t)grow*DD + col] = v;
        }
    }
}

// ---------------------------------------------------------------------------
// Row softmax over S=2048, one warp per row (in-place capable)
// ---------------------------------------------------------------------------
__global__ __launch_bounds__(256)
void softmax_kernel(const float* __restrict__ scores, float* __restrict__ attn) {
    const int row  = blockIdx.x * 8 + (threadIdx.x >> 5);
    const int lane = threadIdx.x & 31;
    const float4* src = (const float4*)(scores + (size_t)row * SS);
    float4*       dst = (float4*)(attn + (size_t)row * SS);

    float4 v[16];
    #pragma unroll
    for (int j = 0; j < 16; j++) v[j] = src[lane + 32*j];

    float m = -3.4e38f;
    #pragma unroll
    for (int j = 0; j < 16; j++)
        m = fmaxf(m, fmaxf(fmaxf(v[j].x, v[j].y), fmaxf(v[j].z, v[j].w)));
    #pragma unroll
    for (int o = 16; o > 0; o >>= 1) m = fmaxf(m, __shfl_xor_sync(0xffffffffu, m, o));

    float sum = 0.f;
    #pragma unroll
    for (int j = 0; j < 16; j++) {
        v[j].x = expf(v[j].x - m); v[j].y = expf(v[j].y - m);
        v[j].z = expf(v[j].z - m); v[j].w = expf(v[j].w - m);
        sum += (v[j].x + v[j].y) + (v[j].z + v[j].w);
    }
    #pragma unroll
    for (int o = 16; o > 0; o >>= 1) sum += __shfl_xor_sync(0xffffffffu, sum, o);

    const float inv = 1.f / sum;
    #pragma unroll
    for (int j = 0; j < 16; j++) {
        v[j].x *= inv; v[j].y *= inv; v[j].z *= inv; v[j].w *= inv;
        dst[lane + 32*j] = v[j];
    }
}

// ---------------------------------------------------------------------------
extern "C" void kernel_launch(void* const* d_in, const int* in_sizes, int n_in,
                              void* d_out, int out_size) {
    const float* inputs  = (const float*)d_in[0];
    const float* context = (const float*)d_in[1];
    const float* mask    = (const float*)d_in[2];
    const float* Wq = (const float*)d_in[3];
    const float* bq = (const float*)d_in[4];
    const float* Wk = (const float*)d_in[5];
    const float* bk = (const float*)d_in[6];
    const float* Wv = (const float*)d_in[7];
    const float* bv = (const float*)d_in[8];
    const float* Wo = (const float*)d_in[9];
    const float* bo = (const float*)d_in[10];

    void* p;
    cudaGetSymbolAddress(&p, g_q);      float* qb = (float*)p;
    cudaGetSymbolAddress(&p, g_k);      float* kb = (float*)p;
    cudaGetSymbolAddress(&p, g_v);      float* vb = (float*)p;
    cudaGetSymbolAddress(&p, g_av);     float* avb = (float*)p;
    cudaGetSymbolAddress(&p, g_scores); float* scratch = (float*)p;

    const size_t OUTN = (size_t)NROWS * DD;
    const size_t ATTN = (size_t)BH * SS * SS;
    const size_t osz = (size_t)out_size;

    float* out_ptr = nullptr;
    float* attn_ptr = nullptr;
    if (osz == OUTN + ATTN)      { out_ptr = (float*)d_out; attn_ptr = (float*)d_out + OUTN; }
    else if (osz == ATTN)        { attn_ptr = (float*)d_out; }
    else                         { out_ptr = (float*)d_out; }

    float* sbuf = attn_ptr ? attn_ptr : scratch;

    dim3 pgrid(DD/128, NROWS/128);
    proj_mma<true ><<<pgrid, 256>>>(inputs,  Wq, bq, qb);   // q (+relpos), tf32 mma
    proj_mma<false><<<pgrid, 256>>>(context, Wk, bk, kb);   // k, tf32 mma
    proj_mma<true ><<<pgrid, 256>>>(context, Wv, bv, vb);   // v (+relpos), tf32 mma

    scores_mma<<<dim3(SS/128, SS/128, BH), 256>>>(mask, sbuf);
    softmax_kernel<<<(BH*SS)/8, 256>>>(sbuf, sbuf);
    av_mma<<<dim3(SS/128, BH), 256>>>(sbuf);

    if (out_ptr)
        proj_kernel<false><<<pgrid, 256>>>(avb, Wo, bo, out_ptr);  // fp32 out-proj
}